// round 6
// baseline (speedup 1.0000x reference)
#include <cuda_runtime.h>

#define Bsz   128
#define Lseq  4096
#define Hd    64
#define G3    192
#define IN2H  128
#define NCLS  230
#define BL    (Bsz * Lseq)

typedef unsigned long long ull;

// Scratch (allocation-free rule: __device__ globals)
__device__ float g_gx[(size_t)2 * BL * G3];    // [dir][b][t][192]  (~805 MB)
__device__ float g_buf0[(size_t)BL * Hd];      // dir0 h: [b][t][64] (~134 MB)
__device__ float g_buf1[(size_t)BL * Hd];      // dir1 h: [b][t][64] (~134 MB)

// ---------------- packed f32x2 / fast-math helpers ----------------
__device__ __forceinline__ ull fma2(ull a, ull b, ull c) {
    ull d;
    asm("fma.rn.f32x2 %0, %1, %2, %3;" : "=l"(d) : "l"(a), "l"(b), "l"(c));
    return d;
}
__device__ __forceinline__ float2 u2f2(ull v) {
    float2 f;
    asm("mov.b64 {%0, %1}, %2;" : "=f"(f.x), "=f"(f.y) : "l"(v));
    return f;
}
__device__ __forceinline__ float tanh_fast(float x) {
    float y;
    asm("tanh.approx.f32 %0, %1;" : "=f"(y) : "f"(x));
    return y;
}
__device__ __forceinline__ float sigm_fast(float x) {
    return fmaf(0.5f, tanh_fast(0.5f * x), 0.5f);
}

// ---------------- gx GEMM for layers 1..3 ----------------
// gx[d][row][c] = sum_k inp[row][k] * w_ih[l-1][d][c][k] + b_ih[l][d][c]
// A (inp) rows: k<64 from g_buf0, k>=64 from g_buf1.
__global__ void __launch_bounds__(256, 1)
gx_gemm_kernel(const float* __restrict__ w_ih,
               const float* __restrict__ b_ih,
               int layer) {
    const int d = blockIdx.y;
    const size_t row0 = (size_t)blockIdx.x * 64;
    const int tid = threadIdx.x;
    const int tx = tid & 15;   // col group: cols tx + 16*j, j<12
    const int ty = tid >> 4;   // row group: rows ty + 16*i, i<4

    const ull* a0 = (const ull*)g_buf0;   // 32 ull per row
    const ull* a1 = (const ull*)g_buf1;
    const ull* w2g =
        (const ull*)(w_ih + ((size_t)(layer - 1) * 2 + d) * G3 * IN2H);

    __shared__ ull a_s[16][65];   // [kpair][row]
    __shared__ ull b_s[16][193];  // [kpair][col]

    ull acc[4][12];
#pragma unroll
    for (int i = 0; i < 4; i++)
#pragma unroll
        for (int j = 0; j < 12; j++) acc[i][j] = 0ULL;

#pragma unroll 1
    for (int ch = 0; ch < 4; ch++) {
        // A tile: 64 rows x 16 pairs
#pragma unroll
        for (int it = 0; it < 4; it++) {
            int lin = tid + it * 256;
            int r = lin >> 4;
            int c2 = lin & 15;
            if (ch < 2)
                a_s[c2][r] = a0[(row0 + r) * 32 + ch * 16 + c2];
            else
                a_s[c2][r] = a1[(row0 + r) * 32 + (ch - 2) * 16 + c2];
        }
        // B tile: 192 cols x 16 pairs (k pairs global: ch*16 + c2)
#pragma unroll
        for (int it = 0; it < 12; it++) {
            int lin = tid + it * 256;
            int cc = lin >> 4;
            int c2 = lin & 15;
            b_s[c2][cc] = w2g[(size_t)cc * 64 + ch * 16 + c2];
        }
        __syncthreads();
#pragma unroll
        for (int kp = 0; kp < 16; kp++) {
            ull a2[4], b2[12];
#pragma unroll
            for (int i = 0; i < 4; i++) a2[i] = a_s[kp][ty + 16 * i];
#pragma unroll
            for (int j = 0; j < 12; j++) b2[j] = b_s[kp][tx + 16 * j];
#pragma unroll
            for (int i = 0; i < 4; i++)
#pragma unroll
                for (int j = 0; j < 12; j++)
                    acc[i][j] = fma2(a2[i], b2[j], acc[i][j]);
        }
        __syncthreads();
    }

    const float* bih = b_ih + ((size_t)layer * 2 + d) * G3;
#pragma unroll
    for (int i = 0; i < 4; i++) {
        size_t row = row0 + ty + 16 * i;
#pragma unroll
        for (int j = 0; j < 12; j++) {
            int c = tx + 16 * j;
            float2 f = u2f2(acc[i][j]);
            g_gx[((size_t)d * BL + row) * G3 + c] = f.x + f.y + bih[c];
        }
    }
}

// ---------------- sequential GRU scan ----------------
// Block = one batch element, blockDim (64, 2): ty = direction, tx = h-component.
// Each thread computes ALL THREE gate dot-products for its component (W rows
// r/z/n resident in registers) -> no gate exchange, single 64-thread named
// barrier per step with a ping-pong h buffer.
__global__ void __launch_bounds__(128)
scan_kernel(const float* __restrict__ w_hh,
            const float* __restrict__ b_hh,
            const float* __restrict__ x,
            const float* __restrict__ w_ih0,
            const float* __restrict__ b_ih,
            int layer) {
    const int b = blockIdx.x;
    const int d = threadIdx.y;
    const int j = threadIdx.x;

    const size_t wbase = ((size_t)layer * 2 + d) * G3;
    const ull* Wr = (const ull*)(w_hh + (wbase + j) * Hd);
    const ull* Wz = (const ull*)(w_hh + (wbase + 64 + j) * Hd);
    const ull* Wn = (const ull*)(w_hh + (wbase + 128 + j) * Hd);
    ull wr[32], wz[32], wn[32];
#pragma unroll
    for (int i = 0; i < 32; i++) { wr[i] = Wr[i]; wz[i] = Wz[i]; wn[i] = Wn[i]; }
    const float br = b_hh[wbase + j];
    const float bz = b_hh[wbase + 64 + j];
    const float bn = b_hh[wbase + 128 + j];

    __shared__ __align__(16) float h_s[2][2][Hd];  // [dir][parity][comp]
    h_s[d][0][j] = 0.0f;
    float hreg = 0.0f;

    const int t0 = (d == 0) ? 0 : (Lseq - 1);
    const int tstep = (d == 0) ? 1 : -1;
    const long gstep = (long)tstep * G3;

    // gx source
    float w0r = 0.f, w0z = 0.f, w0n = 0.f, c0r = 0.f, c0z = 0.f, c0n = 0.f;
    const float* xs = nullptr;
    const float* gp = nullptr;
    if (layer == 0) {
        w0r = w_ih0[d * G3 + j];
        w0z = w_ih0[d * G3 + 64 + j];
        w0n = w_ih0[d * G3 + 128 + j];
        c0r = b_ih[(size_t)d * G3 + j];
        c0z = b_ih[(size_t)d * G3 + 64 + j];
        c0n = b_ih[(size_t)d * G3 + 128 + j];
        xs = x + (size_t)b * Lseq + t0;
    } else {
        gp = g_gx + (((size_t)d * Bsz + b) * Lseq + t0) * G3 + j;
    }
    float* outp = (d == 0 ? g_buf0 : g_buf1) +
                  ((size_t)b * Lseq + (size_t)t0) * Hd + j;
    const long ostep = (long)tstep * Hd;

    // depth-2 prefetch ring
    float qr[2], qz[2], qn[2];
#pragma unroll
    for (int p = 0; p < 2; p++) {
        if (layer == 0) {
            qr[p] = xs[(long)p * tstep];
            qz[p] = 0.f; qn[p] = 0.f;
        } else {
            qr[p] = gp[(long)p * gstep];
            qz[p] = gp[(long)p * gstep + 64];
            qn[p] = gp[(long)p * gstep + 128];
        }
    }

    // initial visibility of h_s[d][0]
    asm volatile("bar.sync %0, %1;" :: "r"(1 + d), "r"(64) : "memory");

#pragma unroll 1
    for (int s = 0; s < Lseq; s++) {
        const int pr = s & 1;
        float ar = qr[pr], az = qz[pr], an = qn[pr];
        const int sp = s + 2;
        if (sp < Lseq) {
            if (layer == 0) {
                qr[pr] = xs[(long)sp * tstep];
            } else {
                qr[pr] = gp[(long)sp * gstep];
                qz[pr] = gp[(long)sp * gstep + 64];
                qn[pr] = gp[(long)sp * gstep + 128];
            }
        }
        float gxr, gxz, gxn;
        if (layer == 0) {
            gxr = fmaf(ar, w0r, c0r);
            gxz = fmaf(ar, w0z, c0z);
            gxn = fmaf(ar, w0n, c0n);
        } else {
            gxr = ar; gxz = az; gxn = an;
        }

        // three 64-long dots vs current h (broadcast LDS, 2 chains/gate)
        const ulonglong2* h4 = (const ulonglong2*)h_s[d][pr];
        ull r0 = 0, r1 = 0, z0 = 0, z1 = 0, n0 = 0, n1 = 0;
#pragma unroll
        for (int i = 0; i < 8; i++) {
            ulonglong2 ha = h4[2 * i];
            ulonglong2 hb = h4[2 * i + 1];
            r0 = fma2(wr[4 * i + 0], ha.x, r0);
            r1 = fma2(wr[4 * i + 1], ha.y, r1);
            z0 = fma2(wz[4 * i + 0], ha.x, z0);
            z1 = fma2(wz[4 * i + 1], ha.y, z1);
            n0 = fma2(wn[4 * i + 0], ha.x, n0);
            n1 = fma2(wn[4 * i + 1], ha.y, n1);
            r0 = fma2(wr[4 * i + 2], hb.x, r0);
            r1 = fma2(wr[4 * i + 3], hb.y, r1);
            z0 = fma2(wz[4 * i + 2], hb.x, z0);
            z1 = fma2(wz[4 * i + 3], hb.y, z1);
            n0 = fma2(wn[4 * i + 2], hb.x, n0);
            n1 = fma2(wn[4 * i + 3], hb.y, n1);
        }
        float2 fr0 = u2f2(r0), fr1 = u2f2(r1);
        float2 fz0 = u2f2(z0), fz1 = u2f2(z1);
        float2 fn0 = u2f2(n0), fn1 = u2f2(n1);
        float ghr = (fr0.x + fr0.y) + (fr1.x + fr1.y) + br;
        float ghz = (fz0.x + fz0.y) + (fz1.x + fz1.y) + bz;
        float ghn = (fn0.x + fn0.y) + (fn1.x + fn1.y) + bn;

        float r = sigm_fast(gxr + ghr);
        float z = sigm_fast(gxz + ghz);
        float n = tanh_fast(fmaf(r, ghn, gxn));
        float hn = fmaf(z, hreg - n, n);   // (1-z)*n + z*h
        hreg = hn;
        h_s[d][pr ^ 1][j] = hn;            // write other buffer (no pre-barrier)
        *outp = hn;
        outp += ostep;
        asm volatile("bar.sync %0, %1;" :: "r"(1 + d), "r"(64) : "memory");
    }
}

// ---------------- final FC on last timestep ----------------
__global__ void fc_kernel(const float* __restrict__ fc_w,
                          const float* __restrict__ fc_b,
                          float* __restrict__ out) {
    int b = blockIdx.x;
    int c = threadIdx.x;
    __shared__ float last[IN2H];
    if (threadIdx.x < Hd)
        last[threadIdx.x] =
            g_buf0[((size_t)b * Lseq + (Lseq - 1)) * Hd + threadIdx.x];
    else if (threadIdx.x < IN2H)
        last[threadIdx.x] =
            g_buf1[((size_t)b * Lseq + (Lseq - 1)) * Hd + threadIdx.x - Hd];
    __syncthreads();
    if (c < NCLS) {
        float s = fc_b[c];
        const float* w = fc_w + (size_t)c * IN2H;
#pragma unroll 8
        for (int k = 0; k < IN2H; k++) s += last[k] * w[k];
        out[(size_t)b * NCLS + c] = s;
    }
}

extern "C" void kernel_launch(void* const* d_in, const int* in_sizes, int n_in,
                              void* d_out, int out_size) {
    const float* x     = (const float*)d_in[0];
    const float* w_ih0 = (const float*)d_in[1];
    const float* w_ih  = (const float*)d_in[2];
    const float* w_hh  = (const float*)d_in[3];
    const float* b_ih  = (const float*)d_in[4];
    const float* b_hh  = (const float*)d_in[5];
    const float* fc_w  = (const float*)d_in[6];
    const float* fc_b  = (const float*)d_in[7];
    float* out = (float*)d_out;

    dim3 sblk(64, 2);
    // Layer 0: gx fused into the scan (input size 1)
    scan_kernel<<<Bsz, sblk>>>(w_hh, b_hh, x, w_ih0, b_ih, 0);
    // Layers 1..3: GEMM input projection, then scan
    for (int l = 1; l < 4; l++) {
        gx_gemm_kernel<<<dim3(BL / 64, 2), 256>>>(w_ih, b_ih, l);
        scan_kernel<<<Bsz, sblk>>>(w_hh, b_hh, x, w_ih0, b_ih, l);
    }
    fc_kernel<<<Bsz, 256>>>(fc_w, fc_b, out);
}

// round 7
// speedup vs baseline: 1.4290x; 1.4290x over previous
#include <cuda_runtime.h>

#define Bsz   128
#define Lseq  4096
#define Hd    64
#define G3    192
#define IN2H  128
#define NCLS  230
#define BL    (Bsz * Lseq)

typedef unsigned long long ull;

// Scratch (allocation-free rule: __device__ globals)
__device__ float g_gx[(size_t)2 * BL * G3];    // [dir][b][t][192]  (~805 MB)
__device__ float g_buf[(size_t)BL * IN2H];     // [b][t][128]       (~268 MB)

// ---------------- packed f32x2 / fast-math helpers ----------------
__device__ __forceinline__ ull fma2(ull a, ull b, ull c) {
    ull d;
    asm("fma.rn.f32x2 %0, %1, %2, %3;" : "=l"(d) : "l"(a), "l"(b), "l"(c));
    return d;
}
__device__ __forceinline__ float2 u2f2(ull v) {
    float2 f;
    asm("mov.b64 {%0, %1}, %2;" : "=f"(f.x), "=f"(f.y) : "l"(v));
    return f;
}
__device__ __forceinline__ float tanh_fast(float x) {
    float y;
    asm("tanh.approx.f32 %0, %1;" : "=f"(y) : "f"(x));
    return y;
}
__device__ __forceinline__ float sigm_fast(float x) {
    return fmaf(0.5f, tanh_fast(0.5f * x), 0.5f);
}
__device__ __forceinline__ unsigned smem_u32(const void* p) {
    return (unsigned)__cvta_generic_to_shared(p);
}
__device__ __forceinline__ void cp_async8(unsigned dst, const void* src) {
    asm volatile("cp.async.ca.shared.global [%0], [%1], 8;"
                 :: "r"(dst), "l"(src));
}
__device__ __forceinline__ void cp_commit() {
    asm volatile("cp.async.commit_group;");
}
template <int N>
__device__ __forceinline__ void cp_wait() {
    asm volatile("cp.async.wait_group %0;" :: "n"(N));
}

// ---------------- gx GEMM for layers 1..3 ----------------
// Tile: 64 rows x 96 cols per CTA, 2 CTAs/SM, cp.async double-buffered K chunks.
// gx[d][row][c] = sum_k inp[row][k] * w_ih[l-1][d][c][k] + b_ih[l][d][c]
__global__ void __launch_bounds__(256, 2)
gx_gemm_kernel(const float* __restrict__ w_ih,
               const float* __restrict__ b_ih,
               int layer) {
    const int d  = blockIdx.x & 1;
    const int c0 = (blockIdx.x >> 1) * 96;       // column half
    const size_t row0 = (size_t)blockIdx.y * 64;
    const int tid = threadIdx.x;
    const int tx = tid & 15;   // cols c0 + tx + 16*j, j<6
    const int ty = tid >> 4;   // rows ty + 16*i, i<4

    const ull* inp2 = (const ull*)g_buf;  // 64 ull per row
    const ull* w2g =
        (const ull*)(w_ih + ((size_t)(layer - 1) * 2 + d) * G3 * IN2H);

    __shared__ ull a_s[2][16][65];   // [buf][kpair][row]
    __shared__ ull b_s[2][16][97];   // [buf][kpair][col]
    const unsigned A_BUF_BYTES = 16 * 65 * 8;
    const unsigned B_BUF_BYTES = 16 * 97 * 8;

    // per-thread load slots (A: 4, B: 6 per chunk)
    unsigned a_dst[4], b_dst[6];
    const ull* a_src[4];
    const ull* b_src[6];
#pragma unroll
    for (int it = 0; it < 4; it++) {
        int lin = tid + it * 256;
        int r = lin >> 4, c2 = lin & 15;
        a_dst[it] = smem_u32(&a_s[0][c2][r]);
        a_src[it] = inp2 + (row0 + r) * 64 + c2;
    }
#pragma unroll
    for (int it = 0; it < 6; it++) {
        int lin = tid + it * 256;
        int cc = lin >> 4, c2 = lin & 15;
        b_dst[it] = smem_u32(&b_s[0][c2][cc]);
        b_src[it] = w2g + (size_t)(c0 + cc) * 64 + c2;
    }

    ull acc[4][6];
#pragma unroll
    for (int i = 0; i < 4; i++)
#pragma unroll
        for (int j = 0; j < 6; j++) acc[i][j] = 0ULL;

    // prologue: chunk 0 -> buf 0
#pragma unroll
    for (int it = 0; it < 4; it++) cp_async8(a_dst[it], a_src[it]);
#pragma unroll
    for (int it = 0; it < 6; it++) cp_async8(b_dst[it], b_src[it]);
    cp_commit();

#pragma unroll
    for (int ch = 0; ch < 4; ch++) {
        const int buf = ch & 1;
        if (ch < 3) {
            const int nb = (ch + 1) & 1;
#pragma unroll
            for (int it = 0; it < 4; it++)
                cp_async8(a_dst[it] + nb * A_BUF_BYTES,
                          a_src[it] + (ch + 1) * 16);
#pragma unroll
            for (int it = 0; it < 6; it++)
                cp_async8(b_dst[it] + nb * B_BUF_BYTES,
                          b_src[it] + (ch + 1) * 16);
            cp_commit();
            cp_wait<1>();   // chunk ch's group retired
        } else {
            cp_wait<0>();
        }
        __syncthreads();
#pragma unroll
        for (int kp = 0; kp < 16; kp++) {
            ull a2[4], b2[6];
#pragma unroll
            for (int i = 0; i < 4; i++) a2[i] = a_s[buf][kp][ty + 16 * i];
#pragma unroll
            for (int j = 0; j < 6; j++) b2[j] = b_s[buf][kp][tx + 16 * j];
#pragma unroll
            for (int i = 0; i < 4; i++)
#pragma unroll
                for (int j = 0; j < 6; j++)
                    acc[i][j] = fma2(a2[i], b2[j], acc[i][j]);
        }
        __syncthreads();
    }

    const float* bih = b_ih + ((size_t)layer * 2 + d) * G3;
#pragma unroll
    for (int i = 0; i < 4; i++) {
        size_t row = row0 + ty + 16 * i;
#pragma unroll
        for (int j = 0; j < 6; j++) {
            int c = c0 + tx + 16 * j;
            float2 f = u2f2(acc[i][j]);
            g_gx[((size_t)d * BL + row) * G3 + c] = f.x + f.y + bih[c];
        }
    }
}

// ---------------- sequential GRU scan (R5 structure, measured-good) ----------
// grid (B, 2 dirs), 192 threads (one per gate output).
// layer 0: gx computed inline from x (input size 1). layers>=1: gx streamed
// from g_gx with a depth-4 register prefetch ring to hide DRAM latency.
__global__ void __launch_bounds__(192, 2)
scan_kernel(const float* __restrict__ w_hh,
            const float* __restrict__ b_hh,
            const float* __restrict__ x,
            const float* __restrict__ w_ih0,
            const float* __restrict__ b_ih,
            int layer) {
    const int b = blockIdx.x;
    const int d = blockIdx.y;
    const int g = threadIdx.x;

    const float* W = w_hh + (((size_t)layer * 2 + d) * G3 + g) * Hd;
    ull w2[32];
#pragma unroll
    for (int i = 0; i < 32; i++) w2[i] = ((const ull*)W)[i];
    const float bias = b_hh[((size_t)layer * 2 + d) * G3 + g];

    __shared__ __align__(16) float h_s[Hd];
    __shared__ float gh_s[G3];
    __shared__ float gx_s[G3];
    if (g < Hd) h_s[g] = 0.0f;
    float hreg = 0.0f;

    const int t0 = (d == 0) ? 0 : (Lseq - 1);
    const int tstep = (d == 0) ? 1 : -1;

    float w0g = 0.0f, bi0 = 0.0f;
    const float* xs = nullptr;
    const float* gxp = nullptr;
    if (layer == 0) {
        w0g = w_ih0[d * G3 + g];
        bi0 = b_ih[d * G3 + g];
        xs = x + (size_t)b * Lseq + t0;
    } else {
        gxp = g_gx + (((size_t)d * Bsz + b) * Lseq + t0) * G3 + g;
    }
    float* outp = g_buf + (size_t)b * Lseq * IN2H + d * Hd + g;
    const long gstep = (long)tstep * G3;

    __syncthreads();

    float q[4];
#pragma unroll
    for (int j = 0; j < 4; j++)
        q[j] = (layer == 0) ? xs[(long)j * tstep] : gxp[(long)j * gstep];

#pragma unroll 1
    for (int s0 = 0; s0 < Lseq; s0 += 4) {
#pragma unroll
        for (int j = 0; j < 4; j++) {
            const int s = s0 + j;
            float raw = q[j];
            const int sp = s + 4;
            if (sp < Lseq)
                q[j] = (layer == 0) ? xs[(long)sp * tstep]
                                    : gxp[(long)sp * gstep];
            float gx_cur = (layer == 0) ? fmaf(raw, w0g, bi0) : raw;

            ull acc0 = 0ULL, acc1 = 0ULL, acc2 = 0ULL, acc3 = 0ULL;
            const ulonglong2* h4 = (const ulonglong2*)h_s;
#pragma unroll
            for (int i = 0; i < 8; i++) {
                ulonglong2 hv0 = h4[2 * i];
                ulonglong2 hv1 = h4[2 * i + 1];
                acc0 = fma2(w2[4 * i + 0], hv0.x, acc0);
                acc1 = fma2(w2[4 * i + 1], hv0.y, acc1);
                acc2 = fma2(w2[4 * i + 2], hv1.x, acc2);
                acc3 = fma2(w2[4 * i + 3], hv1.y, acc3);
            }
            float2 f0 = u2f2(acc0);
            float2 f1 = u2f2(acc1);
            float2 f2 = u2f2(acc2);
            float2 f3 = u2f2(acc3);
            float gh = ((f0.x + f0.y) + (f1.x + f1.y)) +
                       ((f2.x + f2.y) + (f3.x + f3.y)) + bias;

            gh_s[g] = gh;
            gx_s[g] = gx_cur;
            __syncthreads();

            if (g < Hd) {
                float r = sigm_fast(gx_s[g] + gh_s[g]);
                float z = sigm_fast(gx_s[Hd + g] + gh_s[Hd + g]);
                float n = tanh_fast(fmaf(r, gh_s[2 * Hd + g], gx_s[2 * Hd + g]));
                float hn = fmaf(z, hreg - n, n);  // (1-z)n + z*h
                hreg = hn;
                h_s[g] = hn;
                outp[(size_t)(t0 + s * tstep) * IN2H] = hn;
            }
            __syncthreads();
        }
    }
}

// ---------------- final FC on last timestep ----------------
__global__ void fc_kernel(const float* __restrict__ fc_w,
                          const float* __restrict__ fc_b,
                          float* __restrict__ out) {
    int b = blockIdx.x;
    int c = threadIdx.x;
    __shared__ float last[IN2H];
    if (threadIdx.x < IN2H)
        last[threadIdx.x] =
            g_buf[((size_t)b * Lseq + (Lseq - 1)) * IN2H + threadIdx.x];
    __syncthreads();
    if (c < NCLS) {
        float s = fc_b[c];
        const float* w = fc_w + (size_t)c * IN2H;
#pragma unroll 8
        for (int k = 0; k < IN2H; k++) s += last[k] * w[k];
        out[(size_t)b * NCLS + c] = s;
    }
}

extern "C" void kernel_launch(void* const* d_in, const int* in_sizes, int n_in,
                              void* d_out, int out_size) {
    const float* x     = (const float*)d_in[0];
    const float* w_ih0 = (const float*)d_in[1];
    const float* w_ih  = (const float*)d_in[2];
    const float* w_hh  = (const float*)d_in[3];
    const float* b_ih  = (const float*)d_in[4];
    const float* b_hh  = (const float*)d_in[5];
    const float* fc_w  = (const float*)d_in[6];
    const float* fc_b  = (const float*)d_in[7];
    float* out = (float*)d_out;

    // Layer 0: gx fused into the scan (input size 1)
    scan_kernel<<<dim3(Bsz, 2), 192>>>(w_hh, b_hh, x, w_ih0, b_ih, 0);
    // Layers 1..3: GEMM input projection, then scan
    for (int l = 1; l < 4; l++) {
        // grid.x = {d, col-half} so blocks sharing an A row-tile are adjacent
        gx_gemm_kernel<<<dim3(4, BL / 64), 256>>>(w_ih, b_ih, l);
        scan_kernel<<<dim3(Bsz, 2), 192>>>(w_hh, b_hh, x, w_ih0, b_ih, l);
    }
    fc_kernel<<<Bsz, 256>>>(fc_w, fc_b, out);
}